// round 2
// baseline (speedup 1.0000x reference)
#include <cuda_runtime.h>

#define H 28
#define W 28
#define NSQ (H * W)       // 784 pixels
#define OUTER NSQ         // node 784 = outer face (+inf)
#define NN (NSQ + 1)
#define CARD 50

// monotone float->uint mapping (order-preserving)
__device__ __forceinline__ unsigned monof(float x) {
    unsigned u = __float_as_uint(x);
    return (u & 0x80000000u) ? ~u : (u | 0x80000000u);
}

__global__ __launch_bounds__(1024, 1)
void cubical_kernel(const float* __restrict__ I, const float* __restrict__ p,
                    float* __restrict__ out) {
    __shared__ float Ip[NSQ];
    __shared__ short vord[NSQ];      // rank -> vertex
    __shared__ int   pos[NN];        // vertex -> rank (OUTER = -1)
    __shared__ int2  node[NN];       // .x = parent, .y = cmax (float bits)
    __shared__ float pw[NSQ], pd[NSQ];  // pairs: birth (edge weight), death (comp max)
    __shared__ int   npairs;

    const int t = threadIdx.x;
    const float p0 = p[0], p1 = p[1];

    // ---- Phase 1: Ip = I . p, init union-find nodes ----
    if (t < NSQ) {
        float v = fmaf(I[2 * t], p0, I[2 * t + 1] * p1);
        Ip[t] = v;
        node[t] = make_int2(t, __float_as_int(v));
    }
    if (t == 0) {
        node[OUTER] = make_int2(OUTER, __float_as_int(3.0e38f));
        pos[OUTER] = -1;
        npairs = 0;
    }
    __syncthreads();

    // ---- Phase 2: rank pixels descending (ties: index asc), unique ranks ----
    if (t < NSQ) {
        float wi = Ip[t];
        int rank = 0;
        #pragma unroll 4
        for (int j = 0; j < NSQ; j++) {
            float wj = Ip[j];
            rank += (wj > wi) || (wj == wi && j < t);
        }
        vord[rank] = (short)t;
        pos[t] = rank;
    }
    __syncthreads();

    // ---- Phase 3: descending vertex sweep, warp-cooperative union-find ----
    // Superlevel H0 elder rule == reference's dim-1 sublevel pairs:
    //   merge at vertex v: dying component (max M) -> pair (birth=f(v), death=M)
    if (t < 32) {
        const unsigned FULL = 0xffffffffu;
        const int lane = t;
        int np = 0;
        for (int kb = 0; kb < NSQ; kb += 32) {
            int li = kb + lane;
            int vl = vord[li < NSQ ? li : (NSQ - 1)];
            float fl = Ip[vl];
            const int kmax = (NSQ - kb) < 32 ? (NSQ - kb) : 32;
            for (int kk = 0; kk < kmax; kk++) {
                const int v = __shfl_sync(FULL, vl, kk);
                const float fv = __shfl_sync(FULL, fl, kk);
                const int k = kb + kk;
                const int row = v / W;
                const int col = v - row * W;

                int nbr = 0;
                bool valid = false;
                switch (lane) {
                    case 0: nbr = v - 1; valid = (col > 0); break;
                    case 1: nbr = v + 1; valid = (col < W - 1); break;
                    case 2: nbr = v - W; valid = (row > 0); break;
                    case 3: nbr = v + W; valid = (row < H - 1); break;
                    case 4: nbr = OUTER;
                            valid = (col == 0) | (col == W - 1) |
                                    (row == 0) | (row == H - 1);
                            break;
                    default: break;
                }
                bool active = false;
                if (valid) active = (pos[nbr] < k);   // neighbor already entered

                int r = 0;
                float m = 0.0f;
                if (active) {
                    r = nbr;
                    int2 rec = node[r];
                    while (rec.x != r) { r = rec.x; rec = node[r]; }
                    m = __int_as_float(rec.y);
                    if (r != nbr) node[nbr].x = r;    // path compression
                }

                // dedup roots among active lanes
                unsigned key = active ? (unsigned)r : (0x80000000u | (unsigned)lane);
                unsigned mm = __match_any_sync(FULL, key);
                bool rep = active && ((__ffs(mm) - 1) == lane);

                // survivor = rep root with max cmax (outer=+huge always wins)
                unsigned mymono = rep ? monof(m) : 0u;
                unsigned mx = __reduce_max_sync(FULL, mymono);
                unsigned winm = __ballot_sync(FULL, rep && (mymono == mx));
                const bool anyact = (winm != 0);
                const int sl = anyact ? (__ffs(winm) - 1) : 0;
                const int rs = __shfl_sync(FULL, r, sl);

                bool dying = anyact && rep && (lane != sl);
                if (dying) node[r].x = rs;            // merge dying root
                bool emit = dying && (m > fv);        // positive persistence only
                unsigned em = __ballot_sync(FULL, emit);
                if (emit) {
                    int o = np + __popc(em & ((1u << lane) - 1));
                    pw[o] = fv;
                    pd[o] = m;
                }
                np += __popc(em);
                if (anyact && lane == sl) node[v].x = rs;   // attach v to survivor
            }
        }
        if (lane == 0) npairs = np;
    }
    __syncthreads();

    // ---- Phase 5: rank pairs by persistence desc (ties: later index first),
    //      emit top CARD as (birth, death); pad with Ip[0,0] ----
    const int np = npairs;
    if (t < np) {
        float pi = pd[t] - pw[t];
        int rank = 0;
        for (int j = 0; j < np; j++) {
            float pj = pd[j] - pw[j];
            rank += (pj > pi) || (pj == pi && j > t);
        }
        if (rank < CARD) {
            out[2 * rank]     = pw[t];
            out[2 * rank + 1] = pd[t];
        }
    }
    if (t < CARD && t >= np) {
        float pad = Ip[0];
        out[2 * t]     = pad;
        out[2 * t + 1] = pad;
    }
}

extern "C" void kernel_launch(void* const* d_in, const int* in_sizes, int n_in,
                              void* d_out, int out_size) {
    const float* I = (const float*)d_in[0];   // (28,28,2) float32
    const float* p = (const float*)d_in[1];   // (2,1) float32
    float* out = (float*)d_out;               // 100 float32
    (void)in_sizes; (void)n_in; (void)out_size;
    cubical_kernel<<<1, 1024>>>(I, p, out);
}

// round 3
// speedup vs baseline: 3.0973x; 3.0973x over previous
#include <cuda_runtime.h>

#define H 28
#define W 28
#define NSQ (H * W)          // 784 pixel nodes
#define OUTER NSQ            // node 784 = outer face, value +inf
#define NN (NSQ + 1)
#define NE_H (H * (W - 1))   // 756
#define NE_V ((H - 1) * W)   // 756
#define NE_B (2 * H + 2 * W) // 112
#define NE (NE_H + NE_V + NE_B) // 1624
#define NPAD 2048            // bitonic size
#define CARD 50

// monotone float->uint (order-preserving), and inverse
__device__ __forceinline__ unsigned monof(float x) {
    unsigned u = __float_as_uint(x);
    return (u & 0x80000000u) ? ~u : (u | 0x80000000u);
}
__device__ __forceinline__ float invmonof(unsigned m) {
    return __uint_as_float((m & 0x80000000u) ? (m ^ 0x80000000u) : ~m);
}

__global__ __launch_bounds__(1024, 1)
void cubical_kernel(const float* __restrict__ I, const float* __restrict__ p,
                    float* __restrict__ out) {
    __shared__ float Ip[NSQ];
    __shared__ unsigned long long key[NPAD]; // (~monof(w))<<32 | idx  (sort asc)
    __shared__ unsigned uvp[NPAD];           // u<<16 | v payload
    __shared__ int2  node[NN];               // .x = parent, .y = cmax bits
    __shared__ float pw[NSQ], pd[NSQ];       // pairs (birth, death)
    __shared__ int   npairs;

    const int t = threadIdx.x;
    const float p0 = p[0], p1 = p[1];

    // ---- Phase 1: Ip = I . p, node init ----
    if (t < NSQ) {
        float v = fmaf(I[2 * t], p0, I[2 * t + 1] * p1);
        Ip[t] = v;
        node[t] = make_int2(t, __float_as_int(v));
    }
    if (t == 0) {
        node[OUTER] = make_int2(OUTER, __float_as_int(3.0e38f));
        npairs = 0;
    }
    __syncthreads();

    // ---- Phase 2: build packed edge keys ----
    for (int i = t; i < NPAD; i += blockDim.x) {
        if (i < NE) {
            int u, v; float w;
            if (i < NE_H) {                       // horizontal
                int r = i / (W - 1), c = i % (W - 1);
                u = r * W + c; v = u + 1;
                w = fminf(Ip[u], Ip[v]);
            } else if (i < NE_H + NE_V) {         // vertical
                int j = i - NE_H;
                u = j; v = j + W;                 // j = r*W+c directly
                w = fminf(Ip[u], Ip[v]);
            } else {                              // boundary -> OUTER
                int j = i - NE_H - NE_V;
                int sq;
                if (j < W)              sq = j;
                else if (j < 2 * W)     sq = (H - 1) * W + (j - W);
                else if (j < 2 * W + H) sq = (j - 2 * W) * W;
                else                    sq = (j - 2 * W - H) * W + (W - 1);
                u = sq; v = OUTER; w = Ip[sq];
            }
            key[i] = ((unsigned long long)(~monof(w)) << 32) | (unsigned)i;
            uvp[i] = ((unsigned)u << 16) | (unsigned)v;
        } else {
            key[i] = 0xFFFFFFFFFFFFFFFFull;       // pad: sorts last
            uvp[i] = 0;                            // self-loop -> skipped
        }
    }
    __syncthreads();

    // ---- Phase 3: bitonic sort ascending (== weight desc, idx asc) ----
    for (int k2 = 2; k2 <= NPAD; k2 <<= 1) {
        for (int j = k2 >> 1; j >= 1; j >>= 1) {
            int l = ((t & ~(j - 1)) << 1) | (t & (j - 1));
            int m = l | j;
            unsigned long long kl = key[l], km = key[m];
            bool asc = ((l & k2) == 0);
            if ((kl > km) == asc) {
                key[l] = km; key[m] = kl;
                unsigned pl = uvp[l];
                uvp[l] = uvp[m]; uvp[m] = pl;
            }
            __syncthreads();
        }
    }

    // ---- Phase 4: serial Kruskal (weight descending), elder rule ----
    if (t == 0) {
        int np = 0, unions = 0;
        #pragma unroll 1
        for (int k = 0; k < NPAD; k++) {
            unsigned uv = uvp[k];
            int a = (int)(uv >> 16), b = (int)(uv & 0xFFFFu);
            const int u0 = a, v0 = b;
            int2 ra = node[a];
            int2 rb = node[b];
            while (ra.x != a) { a = ra.x; ra = node[a]; }
            while (rb.x != b) { b = rb.x; rb = node[b]; }
            if (a == b) {
                if (u0 != a) node[u0].x = a;       // compress
                if (v0 != a) node[v0].x = a;
                continue;
            }
            float w = invmonof(~(unsigned)(key[k] >> 32));
            float Ma = __int_as_float(ra.y), Mb = __int_as_float(rb.y);
            float die = fminf(Ma, Mb);
            if (die > w) { pw[np] = w; pd[np] = die; np++; }
            int win, lose;
            if (Ma >= Mb) { win = a; lose = b; }
            else          { win = b; lose = a; }
            node[lose].x = win;
            if (u0 != win) node[u0].x = win;       // compress endpoints to root
            if (v0 != win) node[v0].x = win;
            if (++unions == NN - 1) break;
        }
        npairs = np;
    }
    __syncthreads();

    // ---- Phase 5: rank pairs by persistence desc, emit top CARD, pad ----
    const int np = npairs;
    if (t < np) {
        float pi = pd[t] - pw[t];
        int rank = 0;
        for (int j = 0; j < np; j++) {
            float pj = pd[j] - pw[j];
            rank += (pj > pi) || (pj == pi && j > t);
        }
        if (rank < CARD) {
            out[2 * rank]     = pw[t];
            out[2 * rank + 1] = pd[t];
        }
    }
    if (t < CARD && t >= np) {
        float pad = Ip[0];
        out[2 * t]     = pad;
        out[2 * t + 1] = pad;
    }
}

extern "C" void kernel_launch(void* const* d_in, const int* in_sizes, int n_in,
                              void* d_out, int out_size) {
    const float* I = (const float*)d_in[0];   // (28,28,2) float32
    const float* p = (const float*)d_in[1];   // (2,1) float32
    float* out = (float*)d_out;               // 100 float32
    (void)in_sizes; (void)n_in; (void)out_size;
    cubical_kernel<<<1, 1024>>>(I, p, out);
}